// round 1
// baseline (speedup 1.0000x reference)
#include <cuda_runtime.h>
#include <math.h>

// ---------------- scratch (static device globals; no allocation) ----------------
__device__ float g_h1[4096 * 256];                 // relu(msg @ sW1 + sb1)
__device__ float g_h2[4096 * 512];                 // relu(h1 @ sW2 + sb2)
__device__ float g_S [4096u * 4096u];              // tanh(h2 @ sW3 + sb3)   [B, P*P]
__device__ float g_f [4096 * 128];                 // relu(msg @ fW1 + fb1)
__device__ float g_FL[4096 * 256];                 // tanh(f @ fW2 + fb2)    [B, 16*16]

// ---------------- fused GEMM + bias + activation ----------------
// C[M,N] = act(A[M,K] @ W[K,N] + bias[N]); row-major everywhere.
// BM=BN=128, BK=16, 256 threads, 8x8 microtile. Requires M%128==0, N%128==0, K%16==0.
template <int ACT>  // 0 = relu, 1 = tanh
__global__ __launch_bounds__(256) void gemm_act(
    const float* __restrict__ A, const float* __restrict__ W,
    const float* __restrict__ bias, float* __restrict__ C,
    int M, int N, int K)
{
    constexpr int BM = 128, BN = 128, BK = 16;
    __shared__ float As[BK][BM + 4];   // +4 pad: keeps 16B alignment, reduces store conflicts
    __shared__ float Bs[BK][BN];

    const int tid = threadIdx.x;
    const int tx  = tid & 15;          // 0..15 -> N microtile
    const int ty  = tid >> 4;          // 0..15 -> M microtile
    const int bm  = blockIdx.y;
    const int bn  = blockIdx.x;

    const float* Ab = A + (size_t)bm * BM * K;
    const float* Wb = W + (size_t)bn * BN;

    float acc[8][8];
    #pragma unroll
    for (int i = 0; i < 8; i++)
        #pragma unroll
        for (int j = 0; j < 8; j++) acc[i][j] = 0.0f;

    for (int k0 = 0; k0 < K; k0 += BK) {
        // A tile: 128 rows x 16 cols = 512 float4; store transposed As[k][m]
        #pragma unroll
        for (int it = 0; it < 2; it++) {
            int f   = tid + it * 256;
            int row = f >> 2;
            int c4  = (f & 3) * 4;
            float4 v = *reinterpret_cast<const float4*>(Ab + (size_t)row * K + k0 + c4);
            As[c4 + 0][row] = v.x;
            As[c4 + 1][row] = v.y;
            As[c4 + 2][row] = v.z;
            As[c4 + 3][row] = v.w;
        }
        // W tile: 16 rows x 128 cols = 512 float4; direct Bs[k][n]
        #pragma unroll
        for (int it = 0; it < 2; it++) {
            int f   = tid + it * 256;
            int row = f >> 5;
            int c4  = (f & 31) * 4;
            *reinterpret_cast<float4*>(&Bs[row][c4]) =
                *reinterpret_cast<const float4*>(Wb + (size_t)(k0 + row) * N + c4);
        }
        __syncthreads();

        #pragma unroll
        for (int k = 0; k < BK; k++) {
            float a[8], b[8];
            #pragma unroll
            for (int i = 0; i < 8; i++) a[i] = As[k][ty * 8 + i];
            #pragma unroll
            for (int j = 0; j < 8; j++) b[j] = Bs[k][tx * 8 + j];
            #pragma unroll
            for (int i = 0; i < 8; i++)
                #pragma unroll
                for (int j = 0; j < 8; j++) acc[i][j] = fmaf(a[i], b[j], acc[i][j]);
        }
        __syncthreads();
    }

    // epilogue: bias + activation, float4 stores
    #pragma unroll
    for (int i = 0; i < 8; i++) {
        int m = bm * BM + ty * 8 + i;
        #pragma unroll
        for (int j = 0; j < 8; j += 4) {
            int n = bn * BN + tx * 8 + j;
            float4 v;
            float* vv = &v.x;
            #pragma unroll
            for (int t = 0; t < 4; t++) {
                float x = acc[i][j + t] + bias[n + t];
                if (ACT == 0) x = fmaxf(x, 0.0f);
                else          x = tanhf(x);
                vv[t] = x;
            }
            *reinterpret_cast<float4*>(C + (size_t)m * N + n) = v;
        }
    }
}

// ---------------- assemble 3 channels + separable 5x5 Gaussian ----------------
// One CTA per batch image. Channels:
//   c0: spatial = g_S[b]            (64x64)
//   c1: freq    = bilinear upsample of FL[b] (16x16 -> 64x64, align_corners)
//   c2: block   = message bit (p/8, q/8) repeated 8x8
// Then depthwise Gaussian: separable two 5-tap passes with zero padding.
__global__ __launch_bounds__(256) void assemble_conv(
    const float* __restrict__ S, const float* __restrict__ FL,
    const float* __restrict__ msg, float* __restrict__ out)
{
    __shared__ float img[64 * 64];
    __shared__ float tmp[64 * 64];
    __shared__ float fl[256];
    __shared__ float mb[64];
    __shared__ int   loi[64];
    __shared__ float wts[64];

    const int b   = blockIdx.x;
    const int tid = threadIdx.x;

    fl[tid] = FL[(size_t)b * 256 + tid];
    if (tid < 64) {
        mb[tid] = msg[(size_t)b * 64 + tid];
        // align_corners bilinear coords: pos = q * 15 / 63 (exact small ints in fp32)
        float pos = (float)(tid * 15) / 63.0f;
        int lo = (int)floorf(pos);
        loi[tid] = lo;
        wts[tid] = pos - (float)lo;
    }

    // normalized 1D Gaussian taps (sigma=1, ks=5); outer(g,g) already sums to 1
    float g[5];
    {
        float s = 0.0f;
        #pragma unroll
        for (int i = 0; i < 5; i++) {
            float c = (float)(i - 2);
            g[i] = expf(-c * c * 0.5f);
            s += g[i];
        }
        #pragma unroll
        for (int i = 0; i < 5; i++) g[i] /= s;
    }
    __syncthreads();

    #pragma unroll
    for (int c = 0; c < 3; c++) {
        // build channel image
        for (int idx = tid; idx < 4096; idx += 256) {
            int p = idx >> 6, q = idx & 63;
            float v;
            if (c == 0) {
                v = S[(size_t)b * 4096 + idx];
            } else if (c == 1) {
                int lp = loi[p], lq = loi[q];
                int hp = min(lp + 1, 15), hq = min(lq + 1, 15);
                float wp = wts[p], wq = wts[q];
                float v00 = fl[lp * 16 + lq], v01 = fl[lp * 16 + hq];
                float v10 = fl[hp * 16 + lq], v11 = fl[hp * 16 + hq];
                float top = (1.0f - wq) * v00 + wq * v01;
                float bot = (1.0f - wq) * v10 + wq * v11;
                v = (1.0f - wp) * top + wp * bot;
            } else {
                v = mb[((p >> 3) << 3) + (q >> 3)];
            }
            img[idx] = v;
        }
        __syncthreads();

        // horizontal pass (zero pad)
        for (int idx = tid; idx < 4096; idx += 256) {
            int p = idx >> 6, q = idx & 63;
            float s = 0.0f;
            #pragma unroll
            for (int d = -2; d <= 2; d++) {
                int qq = q + d;
                if (qq >= 0 && qq < 64) s = fmaf(g[d + 2], img[(p << 6) + qq], s);
            }
            tmp[idx] = s;
        }
        __syncthreads();

        // vertical pass + store
        for (int idx = tid; idx < 4096; idx += 256) {
            int p = idx >> 6, q = idx & 63;
            float s = 0.0f;
            #pragma unroll
            for (int d = -2; d <= 2; d++) {
                int pp = p + d;
                if (pp >= 0 && pp < 64) s = fmaf(g[d + 2], tmp[(pp << 6) + q], s);
            }
            out[((size_t)b * 3 + c) * 4096 + idx] = s;
        }
        __syncthreads();
    }
}

// ---------------- launch ----------------
extern "C" void kernel_launch(void* const* d_in, const int* in_sizes, int n_in,
                              void* d_out, int out_size)
{
    const float* msg = (const float*)d_in[0];
    const float* sW1 = (const float*)d_in[1];
    const float* sb1 = (const float*)d_in[2];
    const float* sW2 = (const float*)d_in[3];
    const float* sb2 = (const float*)d_in[4];
    const float* sW3 = (const float*)d_in[5];
    const float* sb3 = (const float*)d_in[6];
    const float* fW1 = (const float*)d_in[7];
    const float* fb1 = (const float*)d_in[8];
    const float* fW2 = (const float*)d_in[9];
    const float* fb2 = (const float*)d_in[10];
    float* out = (float*)d_out;

    float *h1, *h2, *S, *f, *FL;
    cudaGetSymbolAddress((void**)&h1, g_h1);
    cudaGetSymbolAddress((void**)&h2, g_h2);
    cudaGetSymbolAddress((void**)&S,  g_S);
    cudaGetSymbolAddress((void**)&f,  g_f);
    cudaGetSymbolAddress((void**)&FL, g_FL);

    dim3 blk(256);
    // spatial chain
    gemm_act<0><<<dim3(256 / 128, 4096 / 128), blk>>>(msg, sW1, sb1, h1, 4096, 256, 64);
    gemm_act<0><<<dim3(512 / 128, 4096 / 128), blk>>>(h1,  sW2, sb2, h2, 4096, 512, 256);
    gemm_act<1><<<dim3(4096 / 128, 4096 / 128), blk>>>(h2, sW3, sb3, S,  4096, 4096, 512);
    // freq chain
    gemm_act<0><<<dim3(128 / 128, 4096 / 128), blk>>>(msg, fW1, fb1, f,  4096, 128, 64);
    gemm_act<1><<<dim3(256 / 128, 4096 / 128), blk>>>(f,   fW2, fb2, FL, 4096, 256, 128);
    // assemble + depthwise Gaussian
    assemble_conv<<<4096, 256>>>(S, FL, msg, out);
}

// round 3
// speedup vs baseline: 1.7043x; 1.7043x over previous
#include <cuda_runtime.h>
#include <cuda_bf16.h>
#include <math.h>
#include <stdint.h>

// ---------------- scratch (static device globals; no allocation) ----------------
__device__ float          g_h1[4096 * 256];
__device__ __nv_bfloat16  g_h2hi[4096 * 512];
__device__ __nv_bfloat16  g_h2lo[4096 * 512];
__device__ __nv_bfloat16  g_W3thi[4096 * 512];   // W3^T hi  [N=4096, K=512]
__device__ __nv_bfloat16  g_W3tlo[4096 * 512];   // W3^T lo
__device__ float          g_S [4096u * 4096u];   // tanh(h2 @ sW3 + sb3)   [B, P*P]
__device__ float          g_f [4096 * 128];
__device__ float          g_FL[4096 * 256];

// ---------------- helpers ----------------
__device__ __forceinline__ uint32_t smem_u32(const void* p) {
    uint32_t a;
    asm("{ .reg .u64 t; cvta.to.shared.u64 t, %1; cvt.u32.u64 %0, t; }" : "=r"(a) : "l"(p));
    return a;
}
__device__ __forceinline__ void cp_async16(uint32_t dst, const void* src) {
    asm volatile("cp.async.cg.shared.global [%0], [%1], 16;" :: "r"(dst), "l"(src));
}
#define CP_COMMIT() asm volatile("cp.async.commit_group;" ::: "memory")

__device__ __forceinline__ void ldsm_x4(uint32_t (&r)[4], uint32_t addr) {
    asm volatile("ldmatrix.sync.aligned.m8n8.x4.shared.b16 {%0,%1,%2,%3}, [%4];"
                 : "=r"(r[0]), "=r"(r[1]), "=r"(r[2]), "=r"(r[3]) : "r"(addr));
}
__device__ __forceinline__ void mma16816(float (&d)[4], const uint32_t (&a)[4],
                                         uint32_t b0, uint32_t b1) {
    asm volatile(
        "mma.sync.aligned.m16n8k16.row.col.f32.bf16.bf16.f32 "
        "{%0,%1,%2,%3}, {%4,%5,%6,%7}, {%8,%9}, {%0,%1,%2,%3};"
        : "+f"(d[0]), "+f"(d[1]), "+f"(d[2]), "+f"(d[3])
        : "r"(a[0]), "r"(a[1]), "r"(a[2]), "r"(a[3]), "r"(b0), "r"(b1));
}

// ---------------- fp32 SIMT GEMM + bias + activation (small layers) ----------------
template <int ACT>  // 0 = relu, 1 = tanh
__global__ __launch_bounds__(256) void gemm_act(
    const float* __restrict__ A, const float* __restrict__ W,
    const float* __restrict__ bias, float* __restrict__ C,
    int M, int N, int K)
{
    constexpr int BM = 128, BN = 128, BK = 16;
    __shared__ float As[BK][BM + 4];
    __shared__ float Bs[BK][BN];

    const int tid = threadIdx.x;
    const int tx  = tid & 15;
    const int ty  = tid >> 4;
    const int bm  = blockIdx.y;
    const int bn  = blockIdx.x;

    const float* Ab = A + (size_t)bm * BM * K;
    const float* Wb = W + (size_t)bn * BN;

    float acc[8][8];
    #pragma unroll
    for (int i = 0; i < 8; i++)
        #pragma unroll
        for (int j = 0; j < 8; j++) acc[i][j] = 0.0f;

    for (int k0 = 0; k0 < K; k0 += BK) {
        #pragma unroll
        for (int it = 0; it < 2; it++) {
            int f   = tid + it * 256;
            int row = f >> 2;
            int c4  = (f & 3) * 4;
            float4 v = *reinterpret_cast<const float4*>(Ab + (size_t)row * K + k0 + c4);
            As[c4 + 0][row] = v.x; As[c4 + 1][row] = v.y;
            As[c4 + 2][row] = v.z; As[c4 + 3][row] = v.w;
        }
        #pragma unroll
        for (int it = 0; it < 2; it++) {
            int f   = tid + it * 256;
            int row = f >> 5;
            int c4  = (f & 31) * 4;
            *reinterpret_cast<float4*>(&Bs[row][c4]) =
                *reinterpret_cast<const float4*>(Wb + (size_t)(k0 + row) * N + c4);
        }
        __syncthreads();
        #pragma unroll
        for (int k = 0; k < BK; k++) {
            float a[8], b[8];
            #pragma unroll
            for (int i = 0; i < 8; i++) a[i] = As[k][ty * 8 + i];
            #pragma unroll
            for (int j = 0; j < 8; j++) b[j] = Bs[k][tx * 8 + j];
            #pragma unroll
            for (int i = 0; i < 8; i++)
                #pragma unroll
                for (int j = 0; j < 8; j++) acc[i][j] = fmaf(a[i], b[j], acc[i][j]);
        }
        __syncthreads();
    }

    #pragma unroll
    for (int i = 0; i < 8; i++) {
        int m = bm * BM + ty * 8 + i;
        #pragma unroll
        for (int j = 0; j < 8; j += 4) {
            int n = bn * BN + tx * 8 + j;
            float4 v; float* vv = &v.x;
            #pragma unroll
            for (int t = 0; t < 4; t++) {
                float x = acc[i][j + t] + bias[n + t];
                if (ACT == 0) x = fmaxf(x, 0.0f); else x = tanhf(x);
                vv[t] = x;
            }
            *reinterpret_cast<float4*>(C + (size_t)m * N + n) = v;
        }
    }
}

// GEMM2 with relu epilogue emitting bf16 hi/lo split (feeds tensor GEMM3)
__global__ __launch_bounds__(256) void gemm_relu_split(
    const float* __restrict__ A, const float* __restrict__ W,
    const float* __restrict__ bias,
    __nv_bfloat16* __restrict__ Chi, __nv_bfloat16* __restrict__ Clo,
    int M, int N, int K)
{
    constexpr int BM = 128, BN = 128, BK = 16;
    __shared__ float As[BK][BM + 4];
    __shared__ float Bs[BK][BN];

    const int tid = threadIdx.x;
    const int tx  = tid & 15;
    const int ty  = tid >> 4;
    const int bm  = blockIdx.y;
    const int bn  = blockIdx.x;

    const float* Ab = A + (size_t)bm * BM * K;
    const float* Wb = W + (size_t)bn * BN;

    float acc[8][8];
    #pragma unroll
    for (int i = 0; i < 8; i++)
        #pragma unroll
        for (int j = 0; j < 8; j++) acc[i][j] = 0.0f;

    for (int k0 = 0; k0 < K; k0 += BK) {
        #pragma unroll
        for (int it = 0; it < 2; it++) {
            int f   = tid + it * 256;
            int row = f >> 2;
            int c4  = (f & 3) * 4;
            float4 v = *reinterpret_cast<const float4*>(Ab + (size_t)row * K + k0 + c4);
            As[c4 + 0][row] = v.x; As[c4 + 1][row] = v.y;
            As[c4 + 2][row] = v.z; As[c4 + 3][row] = v.w;
        }
        #pragma unroll
        for (int it = 0; it < 2; it++) {
            int f   = tid + it * 256;
            int row = f >> 5;
            int c4  = (f & 31) * 4;
            *reinterpret_cast<float4*>(&Bs[row][c4]) =
                *reinterpret_cast<const float4*>(Wb + (size_t)(k0 + row) * N + c4);
        }
        __syncthreads();
        #pragma unroll
        for (int k = 0; k < BK; k++) {
            float a[8], b[8];
            #pragma unroll
            for (int i = 0; i < 8; i++) a[i] = As[k][ty * 8 + i];
            #pragma unroll
            for (int j = 0; j < 8; j++) b[j] = Bs[k][tx * 8 + j];
            #pragma unroll
            for (int i = 0; i < 8; i++)
                #pragma unroll
                for (int j = 0; j < 8; j++) acc[i][j] = fmaf(a[i], b[j], acc[i][j]);
        }
        __syncthreads();
    }

    #pragma unroll
    for (int i = 0; i < 8; i++) {
        int m = bm * BM + ty * 8 + i;
        #pragma unroll
        for (int j = 0; j < 8; j++) {
            int n = bn * BN + tx * 8 + j;
            float x = fmaxf(acc[i][j] + bias[n], 0.0f);
            __nv_bfloat16 hi = __float2bfloat16(x);
            __nv_bfloat16 lo = __float2bfloat16(x - __bfloat162float(hi));
            Chi[(size_t)m * N + n] = hi;
            Clo[(size_t)m * N + n] = lo;
        }
    }
}

// W3 [K=512, N=4096] f32 -> W3^T hi/lo [4096, 512] bf16
__global__ __launch_bounds__(256) void transpose_split(
    const float* __restrict__ W, __nv_bfloat16* __restrict__ Thi,
    __nv_bfloat16* __restrict__ Tlo, int K, int N)
{
    __shared__ float t[32][33];
    int tx = threadIdx.x, ty = threadIdx.y;       // 32 x 8
    int bx = blockIdx.x, by = blockIdx.y;
    #pragma unroll
    for (int i = 0; i < 4; i++) {
        int row = by * 32 + ty + i * 8;
        int col = bx * 32 + tx;
        t[ty + i * 8][tx] = W[(size_t)row * N + col];
    }
    __syncthreads();
    #pragma unroll
    for (int i = 0; i < 4; i++) {
        int n = bx * 32 + ty + i * 8;
        int k = by * 32 + tx;
        float v = t[tx][ty + i * 8];
        __nv_bfloat16 hi = __float2bfloat16(v);
        __nv_bfloat16 lo = __float2bfloat16(v - __bfloat162float(hi));
        Thi[(size_t)n * K + k] = hi;
        Tlo[(size_t)n * K + k] = lo;
    }
}

// ---------------- GEMM3 via legacy mma.sync (bf16 3-split, fp32 accum) ----------------
// S[4096,4096] = tanh(h2[4096,512] @ W3[512,4096] + b3)
// A = h2 hi/lo [M,K] row-major; B = W3^T hi/lo [N,K] row-major ("col" operand).
// CTA: 128x128 tile, 256 threads (8 warps: 4 m-blocks x 2 n-blocks, warp tile 32x64).
// K chunks of 64, cp.async double-buffered, xor-swizzled smem + ldmatrix.
__global__ __launch_bounds__(256, 1) void gemm3_mma(
    const __nv_bfloat16* __restrict__ Ahi, const __nv_bfloat16* __restrict__ Alo,
    const __nv_bfloat16* __restrict__ Bhi, const __nv_bfloat16* __restrict__ Blo,
    const float* __restrict__ bias, float* __restrict__ S)
{
    extern __shared__ char dynsmem[];
    // stage layout: 4 buffers (Ahi,Alo,Bhi,Blo) x 128 rows x 128 bytes (64 bf16)
    // swizzle: 16B chunk c at physical (c ^ (row & 7))
    const uint32_t sbase = smem_u32(dynsmem);

    const int tid  = threadIdx.x;
    const int lane = tid & 31;
    const int wid  = tid >> 5;
    const int wm   = wid & 3;          // m block (32 rows)
    const int wn   = wid >> 2;         // n block (64 cols)
    const int tile_n = blockIdx.x, tile_m = blockIdx.y;

    auto load_chunk = [&](int stage, int kc) {
        const uint32_t st = sbase + stage * 65536;
        #pragma unroll
        for (int it = 0; it < 16; it++) {
            int u   = tid + it * 256;
            int buf = u >> 10;
            int idx = u & 1023;
            int row = idx >> 3;
            int c   = idx & 7;
            uint32_t dst = st + buf * 16384 + row * 128 + ((c ^ (row & 7)) << 4);
            const __nv_bfloat16* src;
            int grow;
            if (buf < 2) { grow = tile_m * 128 + row; src = (buf == 0) ? Ahi : Alo; }
            else         { grow = tile_n * 128 + row; src = (buf == 2) ? Bhi : Blo; }
            cp_async16(dst, (const char*)src + ((size_t)grow * 512 + kc * 64 + c * 8) * 2);
        }
        CP_COMMIT();
    };

    float acc[2][8][4];
    #pragma unroll
    for (int i = 0; i < 2; i++)
        #pragma unroll
        for (int j = 0; j < 8; j++)
            #pragma unroll
            for (int t = 0; t < 4; t++) acc[i][j][t] = 0.0f;

    load_chunk(0, 0);
    load_chunk(1, 1);

    // ldmatrix address precompute (within a stage buffer; add stage+buf offsets later)
    // A x4 (16x16): lanes 0-15 rows m0+lane @ kchunk cb, lanes 16-31 same rows @ cb+1
    const int a_row_in = (lane & 15);
    const int a_cb_add = (lane >> 4);
    // B x4: group g=lane>>3: rows n0 + (g>=2?8:0) + (lane&7), chunk cb + (g&1)
    const int b_row_in = ((lane >> 4) << 3) + (lane & 7);
    const int b_cb_add = (lane >> 3) & 1;

    for (int c = 0; c < 8; ++c) {
        if (c < 7) asm volatile("cp.async.wait_group 1;" ::: "memory");
        else       asm volatile("cp.async.wait_group 0;" ::: "memory");
        __syncthreads();

        const uint32_t st = sbase + (c & 1) * 65536;
        const uint32_t aHiB = st;
        const uint32_t aLoB = st + 16384;
        const uint32_t bHiB = st + 32768;
        const uint32_t bLoB = st + 49152;

        #pragma unroll
        for (int kk = 0; kk < 4; kk++) {          // k16 steps within 64-chunk
            const int cb = kk * 2;
            uint32_t ah[2][4], al[2][4];
            #pragma unroll
            for (int mi = 0; mi < 2; mi++) {
                int row = wm * 32 + mi * 16 + a_row_in;
                uint32_t off = row * 128 + (((cb + a_cb_add) ^ (row & 7)) << 4);
                ldsm_x4(ah[mi], aHiB + off);
                ldsm_x4(al[mi], aLoB + off);
            }
            uint32_t bh[4][4], bl[4][4];
            #pragma unroll
            for (int nq = 0; nq < 4; nq++) {
                int row = wn * 64 + nq * 16 + b_row_in;
                uint32_t off = row * 128 + (((cb + b_cb_add) ^ (row & 7)) << 4);
                ldsm_x4(bh[nq], bHiB + off);
                ldsm_x4(bl[nq], bLoB + off);
            }
            #pragma unroll
            for (int mi = 0; mi < 2; mi++) {
                #pragma unroll
                for (int nq = 0; nq < 4; nq++) {
                    // n-block 2*nq   -> B frag (bh[nq][0], bh[nq][1])
                    // n-block 2*nq+1 -> B frag (bh[nq][2], bh[nq][3])
                    mma16816(acc[mi][2 * nq],     ah[mi], bh[nq][0], bh[nq][1]);
                    mma16816(acc[mi][2 * nq],     ah[mi], bl[nq][0], bl[nq][1]);
                    mma16816(acc[mi][2 * nq],     al[mi], bh[nq][0], bh[nq][1]);
                    mma16816(acc[mi][2 * nq + 1], ah[mi], bh[nq][2], bh[nq][3]);
                    mma16816(acc[mi][2 * nq + 1], ah[mi], bl[nq][2], bl[nq][3]);
                    mma16816(acc[mi][2 * nq + 1], al[mi], bh[nq][2], bh[nq][3]);
                }
            }
        }
        __syncthreads();
        if (c + 2 < 8) load_chunk(c & 1, c + 2);
    }

    // epilogue: bias + tanh, float2 stores
    const int col0 = tile_n * 128 + wn * 64 + (lane & 3) * 2;
    #pragma unroll
    for (int mi = 0; mi < 2; mi++) {
        int r0 = tile_m * 128 + wm * 32 + mi * 16 + (lane >> 2);
        #pragma unroll
        for (int nb = 0; nb < 8; nb++) {
            int col = col0 + nb * 8;
            float b0 = bias[col], b1 = bias[col + 1];
            float2 v0, v1;
            v0.x = tanhf(acc[mi][nb][0] + b0);
            v0.y = tanhf(acc[mi][nb][1] + b1);
            v1.x = tanhf(acc[mi][nb][2] + b0);
            v1.y = tanhf(acc[mi][nb][3] + b1);
            *reinterpret_cast<float2*>(S + (size_t)r0 * 4096 + col) = v0;
            *reinterpret_cast<float2*>(S + (size_t)(r0 + 8) * 4096 + col) = v1;
        }
    }
}

// ---------------- assemble 3 channels + separable 5x5 Gaussian ----------------
__global__ __launch_bounds__(256) void assemble_conv(
    const float* __restrict__ S, const float* __restrict__ FL,
    const float* __restrict__ msg, float* __restrict__ out)
{
    __shared__ float img[64 * 64];
    __shared__ float tmp[64 * 64];
    __shared__ float fl[256];
    __shared__ float mb[64];
    __shared__ int   loi[64];
    __shared__ float wts[64];

    const int b   = blockIdx.x;
    const int tid = threadIdx.x;

    fl[tid] = FL[(size_t)b * 256 + tid];
    if (tid < 64) {
        mb[tid] = msg[(size_t)b * 64 + tid];
        float pos = (float)(tid * 15) / 63.0f;
        int lo = (int)floorf(pos);
        loi[tid] = lo;
        wts[tid] = pos - (float)lo;
    }

    float g[5];
    {
        float s = 0.0f;
        #pragma unroll
        for (int i = 0; i < 5; i++) {
            float c = (float)(i - 2);
            g[i] = expf(-c * c * 0.5f);
            s += g[i];
        }
        #pragma unroll
        for (int i = 0; i < 5; i++) g[i] /= s;
    }
    __syncthreads();

    #pragma unroll
    for (int c = 0; c < 3; c++) {
        for (int idx = tid; idx < 4096; idx += 256) {
            int p = idx >> 6, q = idx & 63;
            float v;
            if (c == 0) {
                v = S[(size_t)b * 4096 + idx];
            } else if (c == 1) {
                int lp = loi[p], lq = loi[q];
                int hp = min(lp + 1, 15), hq = min(lq + 1, 15);
                float wp = wts[p], wq = wts[q];
                float v00 = fl[lp * 16 + lq], v01 = fl[lp * 16 + hq];
                float v10 = fl[hp * 16 + lq], v11 = fl[hp * 16 + hq];
                float top = (1.0f - wq) * v00 + wq * v01;
                float bot = (1.0f - wq) * v10 + wq * v11;
                v = (1.0f - wp) * top + wp * bot;
            } else {
                v = mb[((p >> 3) << 3) + (q >> 3)];
            }
            img[idx] = v;
        }
        __syncthreads();

        for (int idx = tid; idx < 4096; idx += 256) {
            int p = idx >> 6, q = idx & 63;
            float s = 0.0f;
            #pragma unroll
            for (int d = -2; d <= 2; d++) {
                int qq = q + d;
                if (qq >= 0 && qq < 64) s = fmaf(g[d + 2], img[(p << 6) + qq], s);
            }
            tmp[idx] = s;
        }
        __syncthreads();

        for (int idx = tid; idx < 4096; idx += 256) {
            int p = idx >> 6, q = idx & 63;
            float s = 0.0f;
            #pragma unroll
            for (int d = -2; d <= 2; d++) {
                int pp = p + d;
                if (pp >= 0 && pp < 64) s = fmaf(g[d + 2], tmp[(pp << 6) + q], s);
            }
            out[((size_t)b * 3 + c) * 4096 + idx] = s;
        }
        __syncthreads();
    }
}

// ---------------- launch ----------------
extern "C" void kernel_launch(void* const* d_in, const int* in_sizes, int n_in,
                              void* d_out, int out_size)
{
    const float* msg = (const float*)d_in[0];
    const float* sW1 = (const float*)d_in[1];
    const float* sb1 = (const float*)d_in[2];
    const float* sW2 = (const float*)d_in[3];
    const float* sb2 = (const float*)d_in[4];
    const float* sW3 = (const float*)d_in[5];
    const float* sb3 = (const float*)d_in[6];
    const float* fW1 = (const float*)d_in[7];
    const float* fb1 = (const float*)d_in[8];
    const float* fW2 = (const float*)d_in[9];
    const float* fb2 = (const float*)d_in[10];
    float* out = (float*)d_out;

    float *h1, *S, *f, *FL;
    __nv_bfloat16 *h2hi, *h2lo, *w3hi, *w3lo;
    cudaGetSymbolAddress((void**)&h1,   g_h1);
    cudaGetSymbolAddress((void**)&h2hi, g_h2hi);
    cudaGetSymbolAddress((void**)&h2lo, g_h2lo);
    cudaGetSymbolAddress((void**)&w3hi, g_W3thi);
    cudaGetSymbolAddress((void**)&w3lo, g_W3tlo);
    cudaGetSymbolAddress((void**)&S,    g_S);
    cudaGetSymbolAddress((void**)&f,    g_f);
    cudaGetSymbolAddress((void**)&FL,   g_FL);

    cudaFuncSetAttribute(gemm3_mma, cudaFuncAttributeMaxDynamicSharedMemorySize, 131072);

    dim3 blk(256);
    // spatial chain
    gemm_act<0><<<dim3(2, 32), blk>>>(msg, sW1, sb1, h1, 4096, 256, 64);
    gemm_relu_split<<<dim3(4, 32), blk>>>(h1, sW2, sb2, h2hi, h2lo, 4096, 512, 256);
    transpose_split<<<dim3(4096 / 32, 512 / 32), dim3(32, 8)>>>(sW3, w3hi, w3lo, 512, 4096);
    gemm3_mma<<<dim3(32, 32), 256, 131072>>>(h2hi, h2lo, w3hi, w3lo, sb3, S);
    // freq chain
    gemm_act<0><<<dim3(1, 32), blk>>>(msg, fW1, fb1, f, 4096, 128, 64);
    gemm_act<1><<<dim3(2, 32), blk>>>(f, fW2, fb2, FL, 4096, 256, 128);
    // assemble + depthwise Gaussian
    assemble_conv<<<4096, 256>>>(S, FL, msg, out);
}

// round 4
// speedup vs baseline: 1.7942x; 1.0528x over previous
#include <cuda_runtime.h>
#include <cuda_bf16.h>
#include <math.h>
#include <stdint.h>

// ---------------- scratch (static device globals; no allocation) ----------------
__device__ float          g_h1[4096 * 256];
__device__ __nv_bfloat16  g_h2hi[4096 * 512];
__device__ __nv_bfloat16  g_h2lo[4096 * 512];
__device__ __nv_bfloat16  g_W3thi[4096 * 512];   // W3^T hi  [N=4096, K=512]
__device__ __nv_bfloat16  g_W3tlo[4096 * 512];   // W3^T lo
__device__ float          g_S [4096u * 4096u];   // tanh(h2 @ sW3 + sb3)   [B, P*P]
__device__ float          g_f [4096 * 128];
__device__ float          g_FL[4096 * 256];

// ---------------- helpers ----------------
__device__ __forceinline__ uint32_t smem_u32(const void* p) {
    uint32_t a;
    asm("{ .reg .u64 t; cvta.to.shared.u64 t, %1; cvt.u32.u64 %0, t; }" : "=r"(a) : "l"(p));
    return a;
}
__device__ __forceinline__ void cp_async16(uint32_t dst, const void* src) {
    asm volatile("cp.async.cg.shared.global [%0], [%1], 16;" :: "r"(dst), "l"(src));
}
#define CP_COMMIT() asm volatile("cp.async.commit_group;" ::: "memory")

__device__ __forceinline__ void ldsm_x4(uint32_t (&r)[4], uint32_t addr) {
    asm volatile("ldmatrix.sync.aligned.m8n8.x4.shared.b16 {%0,%1,%2,%3}, [%4];"
                 : "=r"(r[0]), "=r"(r[1]), "=r"(r[2]), "=r"(r[3]) : "r"(addr));
}
__device__ __forceinline__ void mma16816(float (&d)[4], const uint32_t (&a)[4],
                                         uint32_t b0, uint32_t b1) {
    asm volatile(
        "mma.sync.aligned.m16n8k16.row.col.f32.bf16.bf16.f32 "
        "{%0,%1,%2,%3}, {%4,%5,%6,%7}, {%8,%9}, {%0,%1,%2,%3};"
        : "+f"(d[0]), "+f"(d[1]), "+f"(d[2]), "+f"(d[3])
        : "r"(a[0]), "r"(a[1]), "r"(a[2]), "r"(a[3]), "r"(b0), "r"(b1));
}

// 64B-row smem layout (4 x 16B chunks/row), swizzled so ldmatrix (8 rows x 16B)
// and cp.async stores are bank-conflict-free:
//   line = row>>1 (128B); idx16 = ((row&1)<<2)|chunk; phys = line*128 + (idx16 ^ (line&7))*16
__device__ __forceinline__ uint32_t swz64(int row, int chunk) {
    int line  = row >> 1;
    int idx16 = ((row & 1) << 2) | chunk;
    return (uint32_t)(line * 128 + ((idx16 ^ (line & 7)) << 4));
}

// ---------------- 64x64-tile fp32 SIMT GEMM + bias + activation ----------------
template <int ACT>  // 0 = relu, 1 = tanh
__global__ __launch_bounds__(256) void gemm64_act(
    const float* __restrict__ A, const float* __restrict__ W,
    const float* __restrict__ bias, float* __restrict__ C,
    int M, int N, int K)
{
    constexpr int BK = 16;
    __shared__ float As[BK][64 + 4];
    __shared__ float Bs[BK][64];

    const int tid = threadIdx.x;
    const int tx  = tid & 15;
    const int ty  = tid >> 4;
    const int bm  = blockIdx.y;
    const int bn  = blockIdx.x;

    const float* Ab = A + (size_t)bm * 64 * K;
    const float* Wb = W + (size_t)bn * 64;

    float acc[4][4];
    #pragma unroll
    for (int i = 0; i < 4; i++)
        #pragma unroll
        for (int j = 0; j < 4; j++) acc[i][j] = 0.0f;

    for (int k0 = 0; k0 < K; k0 += BK) {
        {
            int row = tid >> 2;
            int c4  = (tid & 3) * 4;
            float4 v = *reinterpret_cast<const float4*>(Ab + (size_t)row * K + k0 + c4);
            As[c4 + 0][row] = v.x; As[c4 + 1][row] = v.y;
            As[c4 + 2][row] = v.z; As[c4 + 3][row] = v.w;
        }
        {
            int row = tid >> 4;
            int c4  = (tid & 15) * 4;
            *reinterpret_cast<float4*>(&Bs[row][c4]) =
                *reinterpret_cast<const float4*>(Wb + (size_t)(k0 + row) * N + c4);
        }
        __syncthreads();
        #pragma unroll
        for (int k = 0; k < BK; k++) {
            float a[4], b[4];
            #pragma unroll
            for (int i = 0; i < 4; i++) a[i] = As[k][ty * 4 + i];
            #pragma unroll
            for (int j = 0; j < 4; j++) b[j] = Bs[k][tx * 4 + j];
            #pragma unroll
            for (int i = 0; i < 4; i++)
                #pragma unroll
                for (int j = 0; j < 4; j++) acc[i][j] = fmaf(a[i], b[j], acc[i][j]);
        }
        __syncthreads();
    }

    #pragma unroll
    for (int i = 0; i < 4; i++) {
        int m = bm * 64 + ty * 4 + i;
        int n = bn * 64 + tx * 4;
        float4 v; float* vv = &v.x;
        #pragma unroll
        for (int t = 0; t < 4; t++) {
            float x = acc[i][t] + bias[n + t];
            if (ACT == 0) x = fmaxf(x, 0.0f); else x = tanhf(x);
            vv[t] = x;
        }
        *reinterpret_cast<float4*>(C + (size_t)m * N + n) = v;
    }
}

// 64x64-tile GEMM, relu epilogue emitting bf16 hi/lo split
__global__ __launch_bounds__(256) void gemm64_relu_split(
    const float* __restrict__ A, const float* __restrict__ W,
    const float* __restrict__ bias,
    __nv_bfloat16* __restrict__ Chi, __nv_bfloat16* __restrict__ Clo,
    int M, int N, int K)
{
    constexpr int BK = 16;
    __shared__ float As[BK][64 + 4];
    __shared__ float Bs[BK][64];

    const int tid = threadIdx.x;
    const int tx  = tid & 15;
    const int ty  = tid >> 4;
    const int bm  = blockIdx.y;
    const int bn  = blockIdx.x;

    const float* Ab = A + (size_t)bm * 64 * K;
    const float* Wb = W + (size_t)bn * 64;

    float acc[4][4];
    #pragma unroll
    for (int i = 0; i < 4; i++)
        #pragma unroll
        for (int j = 0; j < 4; j++) acc[i][j] = 0.0f;

    for (int k0 = 0; k0 < K; k0 += BK) {
        {
            int row = tid >> 2;
            int c4  = (tid & 3) * 4;
            float4 v = *reinterpret_cast<const float4*>(Ab + (size_t)row * K + k0 + c4);
            As[c4 + 0][row] = v.x; As[c4 + 1][row] = v.y;
            As[c4 + 2][row] = v.z; As[c4 + 3][row] = v.w;
        }
        {
            int row = tid >> 4;
            int c4  = (tid & 15) * 4;
            *reinterpret_cast<float4*>(&Bs[row][c4]) =
                *reinterpret_cast<const float4*>(Wb + (size_t)(k0 + row) * N + c4);
        }
        __syncthreads();
        #pragma unroll
        for (int k = 0; k < BK; k++) {
            float a[4], b[4];
            #pragma unroll
            for (int i = 0; i < 4; i++) a[i] = As[k][ty * 4 + i];
            #pragma unroll
            for (int j = 0; j < 4; j++) b[j] = Bs[k][tx * 4 + j];
            #pragma unroll
            for (int i = 0; i < 4; i++)
                #pragma unroll
                for (int j = 0; j < 4; j++) acc[i][j] = fmaf(a[i], b[j], acc[i][j]);
        }
        __syncthreads();
    }

    #pragma unroll
    for (int i = 0; i < 4; i++) {
        int m = bm * 64 + ty * 4 + i;
        int n = bn * 64 + tx * 4;
        __nv_bfloat16 hv[4], lv[4];
        #pragma unroll
        for (int t = 0; t < 4; t++) {
            float x = fmaxf(acc[i][t] + bias[n + t], 0.0f);
            hv[t] = __float2bfloat16(x);
            lv[t] = __float2bfloat16(x - __bfloat162float(hv[t]));
        }
        *reinterpret_cast<uint2*>(Chi + (size_t)m * N + n) = *reinterpret_cast<uint2*>(hv);
        *reinterpret_cast<uint2*>(Clo + (size_t)m * N + n) = *reinterpret_cast<uint2*>(lv);
    }
}

// W3 [K=512, N=4096] f32 -> W3^T hi/lo [4096, 512] bf16
__global__ __launch_bounds__(256) void transpose_split(
    const float* __restrict__ W, __nv_bfloat16* __restrict__ Thi,
    __nv_bfloat16* __restrict__ Tlo, int K, int N)
{
    __shared__ float t[32][33];
    int tx = threadIdx.x, ty = threadIdx.y;       // 32 x 8
    int bx = blockIdx.x, by = blockIdx.y;
    #pragma unroll
    for (int i = 0; i < 4; i++) {
        int row = by * 32 + ty + i * 8;
        int col = bx * 32 + tx;
        t[ty + i * 8][tx] = W[(size_t)row * N + col];
    }
    __syncthreads();
    #pragma unroll
    for (int i = 0; i < 4; i++) {
        int n = bx * 32 + ty + i * 8;
        int k = by * 32 + tx;
        float v = t[tx][ty + i * 8];
        __nv_bfloat16 hi = __float2bfloat16(v);
        __nv_bfloat16 lo = __float2bfloat16(v - __bfloat162float(hi));
        Thi[(size_t)n * K + k] = hi;
        Tlo[(size_t)n * K + k] = lo;
    }
}

// ---------------- GEMM3 via mma.sync (bf16 3-split, fp32 accum) ----------------
// S[4096,4096] = tanh(h2[4096,512] @ W3[512,4096] + b3)
// CTA 128x128, 256 thr (8 warps: 4m x 2n, warp tile 32x64).
// K in 16 chunks of 32; 4-stage cp.async ring; ONE barrier per chunk
// (loading chunk c+3 targets the stage chunk c-1 used, which the barrier retired).
__global__ __launch_bounds__(256, 1) void gemm3_mma(
    const __nv_bfloat16* __restrict__ Ahi, const __nv_bfloat16* __restrict__ Alo,
    const __nv_bfloat16* __restrict__ Bhi, const __nv_bfloat16* __restrict__ Blo,
    const float* __restrict__ bias, float* __restrict__ S)
{
    extern __shared__ char dynsmem[];
    // stage = 4 bufs (Ahi,Alo,Bhi,Blo) x 128 rows x 64B (32 bf16) = 32 KB; 4 stages
    const uint32_t sbase = smem_u32(dynsmem);

    const int tid  = threadIdx.x;
    const int lane = tid & 31;
    const int wid  = tid >> 5;
    const int wm   = wid & 3;          // m block (32 rows)
    const int wn   = wid >> 2;         // n block (64 cols)
    const int tile_n = blockIdx.x, tile_m = blockIdx.y;

    auto load_chunk = [&](int stage, int kc) {
        const uint32_t st = sbase + stage * 32768;
        #pragma unroll
        for (int it = 0; it < 8; it++) {
            int u   = tid + it * 256;
            int buf = u >> 9;          // 512 ops per buf
            int idx = u & 511;
            int row = idx >> 2;
            int c   = idx & 3;
            uint32_t dst = st + buf * 8192 + swz64(row, c);
            const __nv_bfloat16* src;
            int grow;
            if (buf < 2) { grow = tile_m * 128 + row; src = (buf == 0) ? Ahi : Alo; }
            else         { grow = tile_n * 128 + row; src = (buf == 2) ? Bhi : Blo; }
            cp_async16(dst, (const char*)src + ((size_t)grow * 512 + kc * 32 + c * 8) * 2);
        }
        CP_COMMIT();
    };

    float acc[2][8][4];
    #pragma unroll
    for (int i = 0; i < 2; i++)
        #pragma unroll
        for (int j = 0; j < 8; j++)
            #pragma unroll
            for (int t = 0; t < 4; t++) acc[i][j][t] = 0.0f;

    load_chunk(0, 0);
    load_chunk(1, 1);
    load_chunk(2, 2);

    // ldmatrix lane mapping (as validated in R3):
    // A x4: lanes 0-15 rows m0+lane @ chunk cb, lanes 16-31 same rows @ cb+1
    const int a_row_in = (lane & 15);
    const int a_cb_add = (lane >> 4);
    // B x4: rows n0 + ((lane>>4)<<3) + (lane&7), chunk cb + ((lane>>3)&1)
    const int b_row_in = ((lane >> 4) << 3) + (lane & 7);
    const int b_cb_add = (lane >> 3) & 1;

    for (int c = 0; c < 16; ++c) {
        // ensure chunk c's cp.async group completed
        switch (15 - c) {
            case 0:  asm volatile("cp.async.wait_group 0;" ::: "memory"); break;
            case 1:  asm volatile("cp.async.wait_group 1;" ::: "memory"); break;
            default: asm volatile("cp.async.wait_group 2;" ::: "memory"); break;
        }
        __syncthreads();

        if (c + 3 < 16) load_chunk((c + 3) & 3, c + 3);

        const uint32_t st = sbase + (c & 3) * 32768;
        const uint32_t aHiB = st;
        const uint32_t aLoB = st + 8192;
        const uint32_t bHiB = st + 16384;
        const uint32_t bLoB = st + 24576;

        #pragma unroll
        for (int kk = 0; kk < 2; kk++) {          // two k16 steps per 32-chunk
            const int cb = kk * 2;
            uint32_t ah[2][4], al[2][4];
            #pragma unroll
            for (int mi = 0; mi < 2; mi++) {
                int row = wm * 32 + mi * 16 + a_row_in;
                uint32_t off = swz64(row, cb + a_cb_add);
                ldsm_x4(ah[mi], aHiB + off);
                ldsm_x4(al[mi], aLoB + off);
            }
            #pragma unroll
            for (int nq = 0; nq < 4; nq++) {
                int row = wn * 64 + nq * 16 + b_row_in;
                uint32_t off = swz64(row, cb + b_cb_add);
                uint32_t bh[4], bl[4];
                ldsm_x4(bh, bHiB + off);
                ldsm_x4(bl, bLoB + off);
                #pragma unroll
                for (int mi = 0; mi < 2; mi++) {
                    mma16816(acc[mi][2 * nq],     ah[mi], bh[0], bh[1]);
                    mma16816(acc[mi][2 * nq],     ah[mi], bl[0], bl[1]);
                    mma16816(acc[mi][2 * nq],     al[mi], bh[0], bh[1]);
                    mma16816(acc[mi][2 * nq + 1], ah[mi], bh[2], bh[3]);
                    mma16816(acc[mi][2 * nq + 1], ah[mi], bl[2], bl[3]);
                    mma16816(acc[mi][2 * nq + 1], al[mi], bh[2], bh[3]);
                }
            }
        }
    }

    // epilogue: bias + tanh, float2 stores
    const int col0 = tile_n * 128 + wn * 64 + (lane & 3) * 2;
    #pragma unroll
    for (int mi = 0; mi < 2; mi++) {
        int r0 = tile_m * 128 + wm * 32 + mi * 16 + (lane >> 2);
        #pragma unroll
        for (int nb = 0; nb < 8; nb++) {
            int col = col0 + nb * 8;
            float b0 = __ldg(bias + col), b1 = __ldg(bias + col + 1);
            float2 v0, v1;
            v0.x = tanhf(acc[mi][nb][0] + b0);
            v0.y = tanhf(acc[mi][nb][1] + b1);
            v1.x = tanhf(acc[mi][nb][2] + b0);
            v1.y = tanhf(acc[mi][nb][3] + b1);
            *reinterpret_cast<float2*>(S + (size_t)r0 * 4096 + col) = v0;
            *reinterpret_cast<float2*>(S + (size_t)(r0 + 8) * 4096 + col) = v1;
        }
    }
}

// ---------------- assemble one channel + separable 5x5 Gaussian ----------------
// grid = (4096 batches, 3 channels); 256 threads.
__global__ __launch_bounds__(256) void assemble_conv(
    const float* __restrict__ S, const float* __restrict__ FL,
    const float* __restrict__ msg, float* __restrict__ out)
{
    __shared__ float img[64 * 64];
    __shared__ float tmp[64 * 64];
    __shared__ float fl[256];

    const int b   = blockIdx.x;
    const int ch  = blockIdx.y;
    const int tid = threadIdx.x;

    float g[5];
    {
        float s = 0.0f;
        #pragma unroll
        for (int i = 0; i < 5; i++) {
            float c = (float)(i - 2);
            g[i] = expf(-c * c * 0.5f);
            s += g[i];
        }
        #pragma unroll
        for (int i = 0; i < 5; i++) g[i] /= s;
    }

    // build channel image
    if (ch == 0) {
        const float4* Sr = reinterpret_cast<const float4*>(S + (size_t)b * 4096);
        float4* I4 = reinterpret_cast<float4*>(img);
        #pragma unroll
        for (int it = 0; it < 4; it++) I4[tid + it * 256] = Sr[tid + it * 256];
    } else if (ch == 1) {
        fl[tid] = FL[(size_t)b * 256 + tid];
        __syncthreads();
        #pragma unroll
        for (int it = 0; it < 16; it++) {
            int idx = tid + it * 256;
            int p = idx >> 6, q = idx & 63;
            float pp = (float)(p * 15) / 63.0f;
            float pq = (float)(q * 15) / 63.0f;
            int lp = (int)pp, lq = (int)pq;
            float wp = pp - (float)lp, wq = pq - (float)lq;
            int hp = min(lp + 1, 15), hq = min(lq + 1, 15);
            float v00 = fl[lp * 16 + lq], v01 = fl[lp * 16 + hq];
            float v10 = fl[hp * 16 + lq], v11 = fl[hp * 16 + hq];
            float top = (1.0f - wq) * v00 + wq * v01;
            float bot = (1.0f - wq) * v10 + wq * v11;
            img[idx] = (1.0f - wp) * top + wp * bot;
        }
    } else {
        if (tid < 64) fl[tid] = msg[(size_t)b * 64 + tid];
        __syncthreads();
        #pragma unroll
        for (int it = 0; it < 16; it++) {
            int idx = tid + it * 256;
            int p = idx >> 6, q = idx & 63;
            img[idx] = fl[((p >> 3) << 3) + (q >> 3)];
        }
    }
    __syncthreads();

    // horizontal pass (zero pad)
    #pragma unroll
    for (int it = 0; it < 16; it++) {
        int idx = tid + it * 256;
        int p = idx >> 6, q = idx & 63;
        float s = 0.0f;
        #pragma unroll
        for (int d = -2; d <= 2; d++) {
            int qq = q + d;
            if (qq >= 0 && qq < 64) s = fmaf(g[d + 2], img[(p << 6) + qq], s);
        }
        tmp[idx] = s;
    }
    __syncthreads();

    // vertical pass + float4 stores
    float* outc = out + ((size_t)b * 3 + ch) * 4096;
    #pragma unroll
    for (int it = 0; it < 4; it++) {
        int i4 = tid + it * 256;          // 0..1023
        int p  = i4 >> 4;
        int q0 = (i4 & 15) << 2;
        float4 s = make_float4(0.f, 0.f, 0.f, 0.f);
        #pragma unroll
        for (int d = -2; d <= 2; d++) {
            int pp = p + d;
            if (pp >= 0 && pp < 64) {
                float4 t4 = *reinterpret_cast<float4*>(&tmp[(pp << 6) + q0]);
                float w = g[d + 2];
                s.x = fmaf(w, t4.x, s.x);
                s.y = fmaf(w, t4.y, s.y);
                s.z = fmaf(w, t4.z, s.z);
                s.w = fmaf(w, t4.w, s.w);
            }
        }
        *reinterpret_cast<float4*>(outc + (p << 6) + q0) = s;
    }
}

// ---------------- launch ----------------
extern "C" void kernel_launch(void* const* d_in, const int* in_sizes, int n_in,
                              void* d_out, int out_size)
{
    const float* msg = (const float*)d_in[0];
    const float* sW1 = (const float*)d_in[1];
    const float* sb1 = (const float*)d_in[2];
    const float* sW2 = (const float*)d_in[3];
    const float* sb2 = (const float*)d_in[4];
    const float* sW3 = (const float*)d_in[5];
    const float* sb3 = (const float*)d_in[6];
    const float* fW1 = (const float*)d_in[7];
    const float* fb1 = (const float*)d_in[8];
    const float* fW2 = (const float*)d_in[9];
    const float* fb2 = (const float*)d_in[10];
    float* out = (float*)d_out;

    float *h1, *S, *f, *FL;
    __nv_bfloat16 *h2hi, *h2lo, *w3hi, *w3lo;
    cudaGetSymbolAddress((void**)&h1,   g_h1);
    cudaGetSymbolAddress((void**)&h2hi, g_h2hi);
    cudaGetSymbolAddress((void**)&h2lo, g_h2lo);
    cudaGetSymbolAddress((void**)&w3hi, g_W3thi);
    cudaGetSymbolAddress((void**)&w3lo, g_W3tlo);
    cudaGetSymbolAddress((void**)&S,    g_S);
    cudaGetSymbolAddress((void**)&f,    g_f);
    cudaGetSymbolAddress((void**)&FL,   g_FL);

    cudaFuncSetAttribute(gemm3_mma, cudaFuncAttributeMaxDynamicSharedMemorySize, 131072);

    dim3 blk(256);
    // spatial chain
    gemm64_act<0><<<dim3(4, 64), blk>>>(msg, sW1, sb1, h1, 4096, 256, 64);
    gemm64_relu_split<<<dim3(8, 64), blk>>>(h1, sW2, sb2, h2hi, h2lo, 4096, 512, 256);
    transpose_split<<<dim3(4096 / 32, 512 / 32), dim3(32, 8)>>>(sW3, w3hi, w3lo, 512, 4096);
    gemm3_mma<<<dim3(32, 32), 256, 131072>>>(h2hi, h2lo, w3hi, w3lo, sb3, S);
    // freq chain
    gemm64_act<0><<<dim3(2, 64), blk>>>(msg, fW1, fb1, f, 4096, 128, 64);
    gemm64_act<1><<<dim3(4, 64), blk>>>(f, fW2, fb2, FL, 4096, 256, 128);
    // assemble + depthwise Gaussian (one channel per CTA)
    assemble_conv<<<dim3(4096, 3), 256>>>(S, FL, msg, out);
}

// round 5
// speedup vs baseline: 1.8893x; 1.0530x over previous
#include <cuda_runtime.h>
#include <cuda_bf16.h>
#include <math.h>
#include <stdint.h>

// ---------------- scratch (static device globals; no allocation) ----------------
__device__ float          g_h1[4096 * 256];
__device__ __nv_bfloat16  g_h2hi[4096 * 512];
__device__ __nv_bfloat16  g_h2lo[4096 * 512];
__device__ __nv_bfloat16  g_W3thi[4096 * 512];   // W3^T hi  [N=4096, K=512]
__device__ __nv_bfloat16  g_W3tlo[4096 * 512];   // W3^T lo
__device__ float          g_S [4096u * 4096u];   // tanh(h2 @ sW3 + sb3)   [B, P*P]
__device__ float          g_f [4096 * 128];
__device__ float          g_FL[4096 * 256];

// ---------------- helpers ----------------
__device__ __forceinline__ uint32_t smem_u32(const void* p) {
    uint32_t a;
    asm("{ .reg .u64 t; cvta.to.shared.u64 t, %1; cvt.u32.u64 %0, t; }" : "=r"(a) : "l"(p));
    return a;
}
__device__ __forceinline__ void cp_async16(uint32_t dst, const void* src) {
    asm volatile("cp.async.cg.shared.global [%0], [%1], 16;" :: "r"(dst), "l"(src));
}
#define CP_COMMIT() asm volatile("cp.async.commit_group;" ::: "memory")

__device__ __forceinline__ void ldsm_x4(uint32_t (&r)[4], uint32_t addr) {
    asm volatile("ldmatrix.sync.aligned.m8n8.x4.shared.b16 {%0,%1,%2,%3}, [%4];"
                 : "=r"(r[0]), "=r"(r[1]), "=r"(r[2]), "=r"(r[3]) : "r"(addr));
}
__device__ __forceinline__ void mma16816(float (&d)[4], const uint32_t (&a)[4],
                                         uint32_t b0, uint32_t b1) {
    asm volatile(
        "mma.sync.aligned.m16n8k16.row.col.f32.bf16.bf16.f32 "
        "{%0,%1,%2,%3}, {%4,%5,%6,%7}, {%8,%9}, {%0,%1,%2,%3};"
        : "+f"(d[0]), "+f"(d[1]), "+f"(d[2]), "+f"(d[3])
        : "r"(a[0]), "r"(a[1]), "r"(a[2]), "r"(a[3]), "r"(b0), "r"(b1));
}

// ---------------- 64x64-tile fp32 SIMT GEMM + bias + activation ----------------
template <int ACT>  // 0 = relu, 1 = tanh
__global__ __launch_bounds__(256) void gemm64_act(
    const float* __restrict__ A, const float* __restrict__ W,
    const float* __restrict__ bias, float* __restrict__ C,
    int M, int N, int K)
{
    constexpr int BK = 16;
    __shared__ float As[BK][64 + 4];
    __shared__ float Bs[BK][64];

    const int tid = threadIdx.x;
    const int tx  = tid & 15;
    const int ty  = tid >> 4;
    const int bm  = blockIdx.y;
    const int bn  = blockIdx.x;

    const float* Ab = A + (size_t)bm * 64 * K;
    const float* Wb = W + (size_t)bn * 64;

    float acc[4][4];
    #pragma unroll
    for (int i = 0; i < 4; i++)
        #pragma unroll
        for (int j = 0; j < 4; j++) acc[i][j] = 0.0f;

    for (int k0 = 0; k0 < K; k0 += BK) {
        {
            int row = tid >> 2;
            int c4  = (tid & 3) * 4;
            float4 v = *reinterpret_cast<const float4*>(Ab + (size_t)row * K + k0 + c4);
            As[c4 + 0][row] = v.x; As[c4 + 1][row] = v.y;
            As[c4 + 2][row] = v.z; As[c4 + 3][row] = v.w;
        }
        {
            int row = tid >> 4;
            int c4  = (tid & 15) * 4;
            *reinterpret_cast<float4*>(&Bs[row][c4]) =
                *reinterpret_cast<const float4*>(Wb + (size_t)(k0 + row) * N + c4);
        }
        __syncthreads();
        #pragma unroll
        for (int k = 0; k < BK; k++) {
            float a[4], b[4];
            #pragma unroll
            for (int i = 0; i < 4; i++) a[i] = As[k][ty * 4 + i];
            #pragma unroll
            for (int j = 0; j < 4; j++) b[j] = Bs[k][tx * 4 + j];
            #pragma unroll
            for (int i = 0; i < 4; i++)
                #pragma unroll
                for (int j = 0; j < 4; j++) acc[i][j] = fmaf(a[i], b[j], acc[i][j]);
        }
        __syncthreads();
    }

    #pragma unroll
    for (int i = 0; i < 4; i++) {
        int m = bm * 64 + ty * 4 + i;
        int n = bn * 64 + tx * 4;
        float4 v; float* vv = &v.x;
        #pragma unroll
        for (int t = 0; t < 4; t++) {
            float x = acc[i][t] + bias[n + t];
            if (ACT == 0) x = fmaxf(x, 0.0f); else x = tanhf(x);
            vv[t] = x;
        }
        *reinterpret_cast<float4*>(C + (size_t)m * N + n) = v;
    }
}

// 64x64-tile GEMM, relu epilogue emitting bf16 hi/lo split
__global__ __launch_bounds__(256) void gemm64_relu_split(
    const float* __restrict__ A, const float* __restrict__ W,
    const float* __restrict__ bias,
    __nv_bfloat16* __restrict__ Chi, __nv_bfloat16* __restrict__ Clo,
    int M, int N, int K)
{
    constexpr int BK = 16;
    __shared__ float As[BK][64 + 4];
    __shared__ float Bs[BK][64];

    const int tid = threadIdx.x;
    const int tx  = tid & 15;
    const int ty  = tid >> 4;
    const int bm  = blockIdx.y;
    const int bn  = blockIdx.x;

    const float* Ab = A + (size_t)bm * 64 * K;
    const float* Wb = W + (size_t)bn * 64;

    float acc[4][4];
    #pragma unroll
    for (int i = 0; i < 4; i++)
        #pragma unroll
        for (int j = 0; j < 4; j++) acc[i][j] = 0.0f;

    for (int k0 = 0; k0 < K; k0 += BK) {
        {
            int row = tid >> 2;
            int c4  = (tid & 3) * 4;
            float4 v = *reinterpret_cast<const float4*>(Ab + (size_t)row * K + k0 + c4);
            As[c4 + 0][row] = v.x; As[c4 + 1][row] = v.y;
            As[c4 + 2][row] = v.z; As[c4 + 3][row] = v.w;
        }
        {
            int row = tid >> 4;
            int c4  = (tid & 15) * 4;
            *reinterpret_cast<float4*>(&Bs[row][c4]) =
                *reinterpret_cast<const float4*>(Wb + (size_t)(k0 + row) * N + c4);
        }
        __syncthreads();
        #pragma unroll
        for (int k = 0; k < BK; k++) {
            float a[4], b[4];
            #pragma unroll
            for (int i = 0; i < 4; i++) a[i] = As[k][ty * 4 + i];
            #pragma unroll
            for (int j = 0; j < 4; j++) b[j] = Bs[k][tx * 4 + j];
            #pragma unroll
            for (int i = 0; i < 4; i++)
                #pragma unroll
                for (int j = 0; j < 4; j++) acc[i][j] = fmaf(a[i], b[j], acc[i][j]);
        }
        __syncthreads();
    }

    #pragma unroll
    for (int i = 0; i < 4; i++) {
        int m = bm * 64 + ty * 4 + i;
        int n = bn * 64 + tx * 4;
        __nv_bfloat16 hv[4], lv[4];
        #pragma unroll
        for (int t = 0; t < 4; t++) {
            float x = fmaxf(acc[i][t] + bias[n + t], 0.0f);
            hv[t] = __float2bfloat16(x);
            lv[t] = __float2bfloat16(x - __bfloat162float(hv[t]));
        }
        *reinterpret_cast<uint2*>(Chi + (size_t)m * N + n) = *reinterpret_cast<uint2*>(hv);
        *reinterpret_cast<uint2*>(Clo + (size_t)m * N + n) = *reinterpret_cast<uint2*>(lv);
    }
}

// W3 [K=512, N=4096] f32 -> W3^T hi/lo [4096, 512] bf16
__global__ __launch_bounds__(256) void transpose_split(
    const float* __restrict__ W, __nv_bfloat16* __restrict__ Thi,
    __nv_bfloat16* __restrict__ Tlo, int K, int N)
{
    __shared__ float t[32][33];
    int tx = threadIdx.x, ty = threadIdx.y;       // 32 x 8
    int bx = blockIdx.x, by = blockIdx.y;
    #pragma unroll
    for (int i = 0; i < 4; i++) {
        int row = by * 32 + ty + i * 8;
        int col = bx * 32 + tx;
        t[ty + i * 8][tx] = W[(size_t)row * N + col];
    }
    __syncthreads();
    #pragma unroll
    for (int i = 0; i < 4; i++) {
        int n = bx * 32 + ty + i * 8;
        int k = by * 32 + tx;
        float v = t[tx][ty + i * 8];
        __nv_bfloat16 hi = __float2bfloat16(v);
        __nv_bfloat16 lo = __float2bfloat16(v - __bfloat162float(hi));
        Thi[(size_t)n * K + k] = hi;
        Tlo[(size_t)n * K + k] = lo;
    }
}

// ---------------- GEMM3 via mma.sync (bf16 3-split, fp32 accum) ----------------
// S[4096,4096] = tanh(h2[4096,512] @ W3[512,4096] + b3)
// CTA 128x128, 256 thr (8 warps: 4m x 2n, warp tile 32x64).
// K in 8 chunks of 64 (128B-row xor swizzle, as in R3 which measured best);
// 3-stage cp.async ring, ONE barrier per chunk:
//   top-of-iter barrier retires chunk c-1 reads (stage (c+2)%3) -> safe to
//   load chunk c+2 there immediately; wait_group allows 2 groups in flight.
__global__ __launch_bounds__(256, 1) void gemm3_mma(
    const __nv_bfloat16* __restrict__ Ahi, const __nv_bfloat16* __restrict__ Alo,
    const __nv_bfloat16* __restrict__ Bhi, const __nv_bfloat16* __restrict__ Blo,
    const float* __restrict__ bias, float* __restrict__ S)
{
    extern __shared__ char dynsmem[];
    // stage = 4 bufs (Ahi,Alo,Bhi,Blo) x 128 rows x 128B (64 bf16) = 64 KB; 3 stages
    const uint32_t sbase = smem_u32(dynsmem);

    const int tid  = threadIdx.x;
    const int lane = tid & 31;
    const int wid  = tid >> 5;
    const int wm   = wid & 3;          // m block (32 rows)
    const int wn   = wid >> 2;         // n block (64 cols)
    const int tile_n = blockIdx.x, tile_m = blockIdx.y;

    auto load_chunk = [&](int stage, int kc) {
        const uint32_t st = sbase + stage * 65536;
        #pragma unroll
        for (int it = 0; it < 16; it++) {
            int u   = tid + it * 256;
            int buf = u >> 10;
            int idx = u & 1023;
            int row = idx >> 3;
            int c   = idx & 7;
            uint32_t dst = st + buf * 16384 + row * 128 + ((c ^ (row & 7)) << 4);
            const __nv_bfloat16* src;
            int grow;
            if (buf < 2) { grow = tile_m * 128 + row; src = (buf == 0) ? Ahi : Alo; }
            else         { grow = tile_n * 128 + row; src = (buf == 2) ? Bhi : Blo; }
            cp_async16(dst, (const char*)src + ((size_t)grow * 512 + kc * 64 + c * 8) * 2);
        }
        CP_COMMIT();
    };

    float acc[2][8][4];
    #pragma unroll
    for (int i = 0; i < 2; i++)
        #pragma unroll
        for (int j = 0; j < 8; j++)
            #pragma unroll
            for (int t = 0; t < 4; t++) acc[i][j][t] = 0.0f;

    load_chunk(0, 0);
    load_chunk(1, 1);

    // ldmatrix lane mapping:
    // A x4: lanes 0-15 rows m0+lane @ 16B-chunk cb, lanes 16-31 same rows @ cb+1
    const int a_row_in = (lane & 15);
    const int a_cb_add = (lane >> 4);
    // B x4: rows n0 + ((lane>>4)<<3) + (lane&7), chunk cb + ((lane>>3)&1)
    const int b_row_in = ((lane >> 4) << 3) + (lane & 7);
    const int b_cb_add = (lane >> 3) & 1;

    for (int c = 0; c < 8; ++c) {
        __syncthreads();                      // retire chunk c-1 reads
        if (c + 2 < 8) load_chunk((c + 2) % 3, c + 2);
        // chunk c's group must be complete; allow 2 groups (c+1, c+2) pending
        switch (7 - c) {
            case 0:  asm volatile("cp.async.wait_group 0;" ::: "memory"); break;
            case 1:  asm volatile("cp.async.wait_group 1;" ::: "memory"); break;
            default: asm volatile("cp.async.wait_group 2;" ::: "memory"); break;
        }

        const uint32_t st = sbase + (c % 3) * 65536;
        const uint32_t aHiB = st;
        const uint32_t aLoB = st + 16384;
        const uint32_t bHiB = st + 32768;
        const uint32_t bLoB = st + 49152;

        #pragma unroll
        for (int kk = 0; kk < 4; kk++) {      // four k16 steps per 64-chunk
            const int cb = kk * 2;
            uint32_t ah[2][4], al[2][4];
            #pragma unroll
            for (int mi = 0; mi < 2; mi++) {
                int row = wm * 32 + mi * 16 + a_row_in;
                uint32_t off = row * 128 + (((cb + a_cb_add) ^ (row & 7)) << 4);
                ldsm_x4(ah[mi], aHiB + off);
                ldsm_x4(al[mi], aLoB + off);
            }
            #pragma unroll
            for (int nq = 0; nq < 4; nq++) {
                int row = wn * 64 + nq * 16 + b_row_in;
                uint32_t off = row * 128 + (((cb + b_cb_add) ^ (row & 7)) << 4);
                uint32_t bh[4], bl[4];
                ldsm_x4(bh, bHiB + off);
                ldsm_x4(bl, bLoB + off);
                #pragma unroll
                for (int mi = 0; mi < 2; mi++) {
                    mma16816(acc[mi][2 * nq],     ah[mi], bh[0], bh[1]);
                    mma16816(acc[mi][2 * nq],     ah[mi], bl[0], bl[1]);
                    mma16816(acc[mi][2 * nq],     al[mi], bh[0], bh[1]);
                    mma16816(acc[mi][2 * nq + 1], ah[mi], bh[2], bh[3]);
                    mma16816(acc[mi][2 * nq + 1], ah[mi], bl[2], bl[3]);
                    mma16816(acc[mi][2 * nq + 1], al[mi], bh[2], bh[3]);
                }
            }
        }
    }

    // epilogue: bias + tanh, float2 stores
    const int col0 = tile_n * 128 + wn * 64 + (lane & 3) * 2;
    #pragma unroll
    for (int mi = 0; mi < 2; mi++) {
        int r0 = tile_m * 128 + wm * 32 + mi * 16 + (lane >> 2);
        #pragma unroll
        for (int nb = 0; nb < 8; nb++) {
            int col = col0 + nb * 8;
            float b0 = __ldg(bias + col), b1 = __ldg(bias + col + 1);
            float2 v0, v1;
            v0.x = tanhf(acc[mi][nb][0] + b0);
            v0.y = tanhf(acc[mi][nb][1] + b1);
            v1.x = tanhf(acc[mi][nb][2] + b0);
            v1.y = tanhf(acc[mi][nb][3] + b1);
            *reinterpret_cast<float2*>(S + (size_t)r0 * 4096 + col) = v0;
            *reinterpret_cast<float2*>(S + (size_t)(r0 + 8) * 4096 + col) = v1;
        }
    }
}

// ---------------- assemble one channel + separable 5x5 Gaussian ----------------
// grid = (4096 batches, 3 channels); 256 threads.
__global__ __launch_bounds__(256) void assemble_conv(
    const float* __restrict__ S, const float* __restrict__ FL,
    const float* __restrict__ msg, float* __restrict__ out)
{
    __shared__ float img[64 * 64];
    __shared__ float tmp[64 * 64];
    __shared__ float fl[256];

    const int b   = blockIdx.x;
    const int ch  = blockIdx.y;
    const int tid = threadIdx.x;

    float g[5];
    {
        float s = 0.0f;
        #pragma unroll
        for (int i = 0; i < 5; i++) {
            float c = (float)(i - 2);
            g[i] = expf(-c * c * 0.5f);
            s += g[i];
        }
        #pragma unroll
        for (int i = 0; i < 5; i++) g[i] /= s;
    }

    // build channel image
    if (ch == 0) {
        const float4* Sr = reinterpret_cast<const float4*>(S + (size_t)b * 4096);
        float4* I4 = reinterpret_cast<float4*>(img);
        #pragma unroll
        for (int it = 0; it < 4; it++) I4[tid + it * 256] = Sr[tid + it * 256];
    } else if (ch == 1) {
        fl[tid] = FL[(size_t)b * 256 + tid];
        __syncthreads();
        #pragma unroll
        for (int it = 0; it < 16; it++) {
            int idx = tid + it * 256;
            int p = idx >> 6, q = idx & 63;
            float pp = (float)(p * 15) / 63.0f;
            float pq = (float)(q * 15) / 63.0f;
            int lp = (int)pp, lq = (int)pq;
            float wp = pp - (float)lp, wq = pq - (float)lq;
            int hp = min(lp + 1, 15), hq = min(lq + 1, 15);
            float v00 = fl[lp * 16 + lq], v01 = fl[lp * 16 + hq];
            float v10 = fl[hp * 16 + lq], v11 = fl[hp * 16 + hq];
            float top = (1.0f - wq) * v00 + wq * v01;
            float bot = (1.0f - wq) * v10 + wq * v11;
            img[idx] = (1.0f - wp) * top + wp * bot;
        }
    } else {
        if (tid < 64) fl[tid] = msg[(size_t)b * 64 + tid];
        __syncthreads();
        #pragma unroll
        for (int it = 0; it < 16; it++) {
            int idx = tid + it * 256;
            int p = idx >> 6, q = idx & 63;
            img[idx] = fl[((p >> 3) << 3) + (q >> 3)];
        }
    }
    __syncthreads();

    // horizontal pass (zero pad)
    #pragma unroll
    for (int it = 0; it < 16; it++) {
        int idx = tid + it * 256;
        int p = idx >> 6, q = idx & 63;
        float s = 0.0f;
        #pragma unroll
        for (int d = -2; d <= 2; d++) {
            int qq = q + d;
            if (qq >= 0 && qq < 64) s = fmaf(g[d + 2], img[(p << 6) + qq], s);
        }
        tmp[idx] = s;
    }
    __syncthreads();

    // vertical pass + float4 stores
    float* outc = out + ((size_t)b * 3 + ch) * 4096;
    #pragma unroll
    for (int it = 0; it < 4; it++) {
        int i4 = tid + it * 256;          // 0..1023
        int p  = i4 >> 4;
        int q0 = (i4 & 15) << 2;
        float4 s = make_float4(0.f, 0.f, 0.f, 0.f);
        #pragma unroll
        for (int d = -2; d <= 2; d++) {
            int pp = p + d;
            if (pp >= 0 && pp < 64) {
                float4 t4 = *reinterpret_cast<float4*>(&tmp[(pp << 6) + q0]);
                float w = g[d + 2];
                s.x = fmaf(w, t4.x, s.x);
                s.y = fmaf(w, t4.y, s.y);
                s.z = fmaf(w, t4.z, s.z);
                s.w = fmaf(w, t4.w, s.w);
            }
        }
        *reinterpret_cast<float4*>(outc + (p << 6) + q0) = s;
    }
}

// ---------------- launch ----------------
extern "C" void kernel_launch(void* const* d_in, const int* in_sizes, int n_in,
                              void* d_out, int out_size)
{
    const float* msg = (const float*)d_in[0];
    const float* sW1 = (const float*)d_in[1];
    const float* sb1 = (const float*)d_in[2];
    const float* sW2 = (const float*)d_in[3];
    const float* sb2 = (const float*)d_in[4];
    const float* sW3 = (const float*)d_in[5];
    const float* sb3 = (const float*)d_in[6];
    const float* fW1 = (const float*)d_in[7];
    const float* fb1 = (const float*)d_in[8];
    const float* fW2 = (const float*)d_in[9];
    const float* fb2 = (const float*)d_in[10];
    float* out = (float*)d_out;

    float *h1, *S, *f, *FL;
    __nv_bfloat16 *h2hi, *h2lo, *w3hi, *w3lo;
    cudaGetSymbolAddress((void**)&h1,   g_h1);
    cudaGetSymbolAddress((void**)&h2hi, g_h2hi);
    cudaGetSymbolAddress((void**)&h2lo, g_h2lo);
    cudaGetSymbolAddress((void**)&w3hi, g_W3thi);
    cudaGetSymbolAddress((void**)&w3lo, g_W3tlo);
    cudaGetSymbolAddress((void**)&S,    g_S);
    cudaGetSymbolAddress((void**)&f,    g_f);
    cudaGetSymbolAddress((void**)&FL,   g_FL);

    cudaFuncSetAttribute(gemm3_mma, cudaFuncAttributeMaxDynamicSharedMemorySize, 196608);

    dim3 blk(256);
    // spatial chain
    gemm64_act<0><<<dim3(4, 64), blk>>>(msg, sW1, sb1, h1, 4096, 256, 64);
    gemm64_relu_split<<<dim3(8, 64), blk>>>(h1, sW2, sb2, h2hi, h2lo, 4096, 512, 256);
    transpose_split<<<dim3(4096 / 32, 512 / 32), dim3(32, 8)>>>(sW3, w3hi, w3lo, 512, 4096);
    gemm3_mma<<<dim3(32, 32), 256, 196608>>>(h2hi, h2lo, w3hi, w3lo, sb3, S);
    // freq chain
    gemm64_act<0><<<dim3(2, 64), blk>>>(msg, fW1, fb1, f, 4096, 128, 64);
    gemm64_act<1><<<dim3(4, 64), blk>>>(f, fW2, fb2, FL, 4096, 256, 128);
    // assemble + depthwise Gaussian (one channel per CTA)
    assemble_conv<<<dim3(4096, 3), 256>>>(S, FL, msg, out);
}